// round 1
// baseline (speedup 1.0000x reference)
#include <cuda_runtime.h>

#define B_ 128
#define T_ 1024
#define N_ 64

// Per-batch losses; reduced deterministically by a second kernel.
__device__ float g_loss[B_];

__global__ void __launch_bounds__(N_, 1) crf_forward_kernel(
    const float* __restrict__ pot,     // (B,T,N)
    const int*   __restrict__ tags,    // (B,T)
    const int*   __restrict__ seqlen,  // (B,)
    const float* __restrict__ ck,      // (N,N)
    const float* __restrict__ sw)      // (B,)
{
    const int b = blockIdx.x;
    const int j = threadIdx.x;
    const int len = seqlen[b];

    __shared__ float abuf[2][N_];
    __shared__ float red[N_];

    // Column j of E = exp(chain_kernel), kept in registers (64 regs).
    float Ecol[N_];
#pragma unroll
    for (int i = 0; i < N_; ++i) Ecol[i] = __expf(ck[i * N_ + j]);

    const float* Pb   = pot  + (size_t)b * T_ * N_;
    const int*   tagb = tags + b * T_;

    // ---------------- sequence score ----------------
    float ss = 0.f;
    for (int t = j; t < len; t += N_) {
        int tg = tagb[t];
        ss += Pb[t * N_ + tg];
        if (t >= 1) ss += ck[tagb[t - 1] * N_ + tg];
    }
    red[j] = ss;
    __syncthreads();
#pragma unroll
    for (int off = N_ / 2; off >= 1; off >>= 1) {
        if (j < off) red[j] += red[j + off];
        __syncthreads();
    }
    const float seq_score = red[0];

    // ---------------- forward scan (linear domain + running log offset) ----
    // alpha_t[j] = c + log(a[j]).  Init: alpha_0 = pot[b,0,:], offset by pot[b,0,0].
    float c = Pb[0];
    abuf[0][j] = __expf(Pb[j] - c);
    __syncthreads();

    // Prefetch potentials two steps ahead to hide DRAM latency.
    float p_cur = Pb[1 * N_ + j];                       // len >= 2 always (len >= T/2)
    float p_nxt = (2 < len) ? Pb[2 * N_ + j] : 0.f;

    int cur = 0;
    for (int t = 1; t < len; ++t) {
        float p_pref = (t + 2 < len) ? Pb[(t + 2) * N_ + j] : 0.f;

        const float* rd = abuf[cur];
        float a0   = rd[0];                    // broadcast LDS
        float r    = __fdividef(1.0f, a0);     // off the FMA critical path
        float epot = __expf(p_cur);            // operand prefetched last iter

        const float4* a4 = (const float4*)rd;
        float s0 = 0.f, s1 = 0.f, s2 = 0.f, s3 = 0.f;
#pragma unroll
        for (int i4 = 0; i4 < N_ / 4; ++i4) {
            float4 av = a4[i4];
            s0 = fmaf(av.x, Ecol[4 * i4 + 0], s0);
            s1 = fmaf(av.y, Ecol[4 * i4 + 1], s1);
            s2 = fmaf(av.z, Ecol[4 * i4 + 2], s2);
            s3 = fmaf(av.w, Ecol[4 * i4 + 3], s3);
        }
        float s = (s0 + s1) + (s2 + s3);

        abuf[cur ^ 1][j] = s * r * epot;       // write other buffer: single barrier
        c += __logf(a0);                       // independent accumulator chain
        __syncthreads();
        cur ^= 1;
        p_cur = p_nxt;
        p_nxt = p_pref;
    }

    // log_norm = c + log(sum_j a[j])
    red[j] = abuf[cur][j];
    __syncthreads();
#pragma unroll
    for (int off = N_ / 2; off >= 1; off >>= 1) {
        if (j < off) red[j] += red[j + off];
        __syncthreads();
    }

    if (j == 0) {
        float log_norm = c + logf(red[0]);
        g_loss[b] = -(seq_score - log_norm) * sw[b];
    }
}

__global__ void crf_finalize_kernel(float* __restrict__ out)
{
    __shared__ float r[B_];
    int j = threadIdx.x;
    r[j] = g_loss[j];
    __syncthreads();
#pragma unroll
    for (int off = B_ / 2; off >= 1; off >>= 1) {
        if (j < off) r[j] += r[j + off];
        __syncthreads();
    }
    if (j == 0) out[0] = r[0] * (1.0f / (float)B_);
}

extern "C" void kernel_launch(void* const* d_in, const int* in_sizes, int n_in,
                              void* d_out, int out_size)
{
    const float* pot    = (const float*)d_in[0];
    const int*   tags   = (const int*)  d_in[1];
    const int*   seqlen = (const int*)  d_in[2];
    const float* ck     = (const float*)d_in[3];
    const float* sw     = (const float*)d_in[4];

    crf_forward_kernel<<<B_, N_>>>(pot, tags, seqlen, ck, sw);
    crf_finalize_kernel<<<1, B_>>>((float*)d_out);
}

// round 2
// speedup vs baseline: 1.3972x; 1.3972x over previous
#include <cuda_runtime.h>

#define B_ 128
#define T_ 1024
#define N_ 64

// Per-batch losses; reduced deterministically by a second kernel.
__device__ float g_loss[B_];

typedef unsigned long long u64;

__device__ __forceinline__ u64 pack2(float lo, float hi) {
    u64 d;
    asm("mov.b64 %0, {%1, %2};" : "=l"(d)
        : "r"(__float_as_uint(lo)), "r"(__float_as_uint(hi)));
    return d;
}
__device__ __forceinline__ float unpack_sum(u64 v) {
    unsigned a, b;
    asm("mov.b64 {%0, %1}, %2;" : "=r"(a), "=r"(b) : "l"(v));
    return __uint_as_float(a) + __uint_as_float(b);
}
__device__ __forceinline__ u64 ffma2(u64 a, u64 b, u64 c) {
    u64 d;
    asm("fma.rn.f32x2 %0, %1, %2, %3;" : "=l"(d) : "l"(a), "l"(b), "l"(c));
    return d;
}
__device__ __forceinline__ u64 fadd2(u64 a, u64 b) {
    u64 d;
    asm("add.rn.f32x2 %0, %1, %2;" : "=l"(d) : "l"(a), "l"(b));
    return d;
}

__global__ void __launch_bounds__(N_, 1) crf_forward_kernel(
    const float* __restrict__ pot,     // (B,T,N)
    const int*   __restrict__ tags,    // (B,T)
    const int*   __restrict__ seqlen,  // (B,)
    const float* __restrict__ ck,      // (N,N)
    const float* __restrict__ sw)      // (B,)
{
    const int b = blockIdx.x;
    const int j = threadIdx.x;
    const int len = seqlen[b];

    __shared__ __align__(16) float abuf[2][N_];
    __shared__ float red[N_];

    // Column j of E = exp(chain_kernel), packed as 32 f32x2 pairs (rows 2i, 2i+1).
    u64 Ec[N_ / 2];
#pragma unroll
    for (int i = 0; i < N_ / 2; ++i)
        Ec[i] = pack2(__expf(ck[(2 * i) * N_ + j]),
                      __expf(ck[(2 * i + 1) * N_ + j]));

    const float* Pb   = pot  + (size_t)b * T_ * N_;
    const int*   tagb = tags + b * T_;

    // ---------------- sequence score ----------------
    float ss = 0.f;
    for (int t = j; t < len; t += N_) {
        int tg = tagb[t];
        ss += Pb[t * N_ + tg];
        if (t >= 1) ss += ck[tagb[t - 1] * N_ + tg];
    }
    red[j] = ss;
    __syncthreads();
#pragma unroll
    for (int off = N_ / 2; off >= 1; off >>= 1) {
        if (j < off) red[j] += red[j + off];
        __syncthreads();
    }
    const float seq_score = red[0];

    // ---------------- forward scan (linear domain + running log offset) ----
    // alpha_t[j] = c + log(a[j]); renormalize by a[0] every step.
    float c = Pb[0];
    abuf[0][j] = __expf(Pb[j] - c);
    __syncthreads();

    // Prefetch potentials two steps ahead (len >= T/2 >= 2 always).
    float p_cur = Pb[1 * N_ + j];
    float p_nxt = (2 < len) ? Pb[2 * N_ + j] : 0.f;

    int cur = 0;
    for (int t = 1; t < len; ++t) {
        float p_pref = (t + 2 < len) ? Pb[(t + 2) * N_ + j] : 0.f;

        const float* rd = abuf[cur];
        float a0    = rd[0];                              // broadcast LDS
        float scale = __fdividef(1.0f, a0) * __expf(p_cur); // off critical path

        // Packed matvec: s_j = sum_i a_i * E[i][j], 16x FFMA2, depth 4.
        const ulonglong2* a4 = (const ulonglong2*)rd;
        u64 acc[8];
#pragma unroll
        for (int m = 0; m < 8; ++m) acc[m] = 0ull;        // {0.f, 0.f}
#pragma unroll
        for (int k = 0; k < 16; ++k) {
            ulonglong2 v = a4[k];                          // floats 4k..4k+3
            acc[(2 * k)     & 7] = ffma2(v.x, Ec[2 * k],     acc[(2 * k)     & 7]);
            acc[(2 * k + 1) & 7] = ffma2(v.y, Ec[2 * k + 1], acc[(2 * k + 1) & 7]);
        }
        acc[0] = fadd2(acc[0], acc[1]);
        acc[2] = fadd2(acc[2], acc[3]);
        acc[4] = fadd2(acc[4], acc[5]);
        acc[6] = fadd2(acc[6], acc[7]);
        acc[0] = fadd2(acc[0], acc[2]);
        acc[4] = fadd2(acc[4], acc[6]);
        acc[0] = fadd2(acc[0], acc[4]);
        float s = unpack_sum(acc[0]);

        abuf[cur ^ 1][j] = s * scale;   // single multiply on the critical path
        c += __logf(a0);                // independent accumulator chain
        __syncthreads();
        cur ^= 1;
        p_cur = p_nxt;
        p_nxt = p_pref;
    }

    // log_norm = c + log(sum_j a[j])
    red[j] = abuf[cur][j];
    __syncthreads();
#pragma unroll
    for (int off = N_ / 2; off >= 1; off >>= 1) {
        if (j < off) red[j] += red[j + off];
        __syncthreads();
    }

    if (j == 0) {
        float log_norm = c + logf(red[0]);
        g_loss[b] = -(seq_score - log_norm) * sw[b];
    }
}

__global__ void crf_finalize_kernel(float* __restrict__ out)
{
    __shared__ float r[B_];
    int j = threadIdx.x;
    r[j] = g_loss[j];
    __syncthreads();
#pragma unroll
    for (int off = B_ / 2; off >= 1; off >>= 1) {
        if (j < off) r[j] += r[j + off];
        __syncthreads();
    }
    if (j == 0) out[0] = r[0] * (1.0f / (float)B_);
}

extern "C" void kernel_launch(void* const* d_in, const int* in_sizes, int n_in,
                              void* d_out, int out_size)
{
    const float* pot    = (const float*)d_in[0];
    const int*   tags   = (const int*)  d_in[1];
    const int*   seqlen = (const int*)  d_in[2];
    const float* ck     = (const float*)d_in[3];
    const float* sw     = (const float*)d_in[4];

    crf_forward_kernel<<<B_, N_>>>(pot, tags, seqlen, ck, sw);
    crf_finalize_kernel<<<1, B_>>>((float*)d_out);
}